// round 7
// baseline (speedup 1.0000x reference)
#include <cuda_runtime.h>
#include <cuda_bf16.h>
#include <cstdint>

// ---------------- problem constants ----------------
#define MAX_N 50000
#define MAX_E 800000
#define D 128
#define CAP 96          // bucket slots per node (deg ~ Poisson(16))

// ---------------- device-global scratch ----------------
__device__ int g_cursor[MAX_N];
__device__ int g_bucket[(size_t)MAX_N * CAP];
// bf16 hi/lo feature planes, each [node][64] u32 (= 128 bf16 per row, 256B)
__device__ __align__(128) uint32_t g_xh[(size_t)MAX_N * 64];
__device__ __align__(128) uint32_t g_xl[(size_t)MAX_N * 64];
__device__ __align__(128) uint32_t g_hh[(size_t)MAX_N * 64];
__device__ __align__(128) uint32_t g_hl[(size_t)MAX_N * 64];
// fp32 copy of h for layer-2 gather (vectorized LDG.128)
__device__ __align__(128) float g_hf[(size_t)MAX_N * D];
// bf16 hi/lo weight images, transposed: [layer][chunk(8)][n=128][k=32]
__device__ __align__(128) __nv_bfloat16 g_Bh[2][8][128 * 32];
__device__ __align__(128) __nv_bfloat16 g_Bl[2][8][128 * 32];

// ---------------- small helpers ----------------
__device__ __forceinline__ uint32_t pack_bf2(float a, float b) {
    __nv_bfloat162 t;
    t.x = __float2bfloat16(a);
    t.y = __float2bfloat16(b);
    return *reinterpret_cast<uint32_t*>(&t);
}
__device__ __forceinline__ float bf_res(float v) {
    return v - __bfloat162float(__float2bfloat16(v));
}
__device__ __forceinline__ uint32_t smem_u32(const void* p) {
    uint32_t a;
    asm("{ .reg .u64 t; cvta.to.shared.u64 t, %1; cvt.u32.u64 %0, t; }" : "=r"(a) : "l"(p));
    return a;
}
__device__ __forceinline__ void ldm_x4(uint32_t* r, uint32_t addr) {
    asm volatile("ldmatrix.sync.aligned.m8n8.x4.shared.b16 {%0,%1,%2,%3}, [%4];"
                 : "=r"(r[0]), "=r"(r[1]), "=r"(r[2]), "=r"(r[3]) : "r"(addr));
}
__device__ __forceinline__ void mma16816(float* d, const uint32_t* a, uint32_t b0, uint32_t b1) {
    asm volatile("mma.sync.aligned.m16n8k16.row.col.f32.bf16.bf16.f32 "
                 "{%0,%1,%2,%3}, {%4,%5,%6,%7}, {%8,%9}, {%0,%1,%2,%3};"
                 : "+f"(d[0]), "+f"(d[1]), "+f"(d[2]), "+f"(d[3])
                 : "r"(a[0]), "r"(a[1]), "r"(a[2]), "r"(a[3]), "r"(b0), "r"(b1));
}
__device__ __forceinline__ void cp16(uint32_t dst, const void* src, uint32_t sz) {
    asm volatile("cp.async.cg.shared.global [%0], [%1], 16, %2;"
                 :: "r"(dst), "l"(src), "r"(sz) : "memory");
}
#define CP_COMMIT()  asm volatile("cp.async.commit_group;" ::: "memory")
#define CP_WAIT(N)   asm volatile("cp.async.wait_group %0;" :: "n"(N) : "memory")
#define BAR_ARRIVE_1_512() asm volatile("bar.arrive 1, 512;" ::: "memory")
#define BAR_SYNC_1_512()   asm volatile("bar.sync 1, 512;" ::: "memory")
#define BAR_SYNC_2_256()   asm volatile("bar.sync 2, 256;" ::: "memory")

// XOR swizzle: 64B rows, 4x16B chunks; conflict-free for ldmatrix
#define SWZ(row, ci) (((uint32_t)(row) << 6) + (((((ci) ^ ((row) >> 1)) & 3)) << 4))

// ---------------- graph build: single-pass bucket scatter ----------------
__global__ void k_zero(int n) {
    int i = blockIdx.x * blockDim.x + threadIdx.x;
    if (i < n) g_cursor[i] = 0;
}
__global__ void k_scatter(const int* __restrict__ ei, int E, int n) {
    int t = blockIdx.x * blockDim.x + threadIdx.x;   // handles 4 edges
    if (t < E / 4) {
        int4 sp = ((const int4*)ei)[t];
        int4 dp = ((const int4*)(ei + E))[t];
        int d0 = min(max(dp.x, 0), n - 1), s0 = min(max(sp.x, 0), n - 1);
        int d1 = min(max(dp.y, 0), n - 1), s1 = min(max(sp.y, 0), n - 1);
        int d2 = min(max(dp.z, 0), n - 1), s2 = min(max(sp.z, 0), n - 1);
        int d3 = min(max(dp.w, 0), n - 1), s3 = min(max(sp.w, 0), n - 1);
        int p0 = atomicAdd(&g_cursor[d0], 1);
        int p1 = atomicAdd(&g_cursor[d1], 1);
        int p2 = atomicAdd(&g_cursor[d2], 1);
        int p3 = atomicAdd(&g_cursor[d3], 1);
        if (p0 < CAP) g_bucket[(size_t)d0 * CAP + p0] = s0;
        if (p1 < CAP) g_bucket[(size_t)d1 * CAP + p1] = s1;
        if (p2 < CAP) g_bucket[(size_t)d2 * CAP + p2] = s2;
        if (p3 < CAP) g_bucket[(size_t)d3 * CAP + p3] = s3;
    }
}

// ---------------- x -> bf16 hi/lo planes ----------------
__global__ void k_split_x(const float* __restrict__ x, int total64) {
    int i = blockIdx.x * blockDim.x + threadIdx.x;
    if (i < total64) {
        float2 v = ((const float2*)x)[i];
        g_xh[i] = pack_bf2(v.x, v.y);
        g_xl[i] = pack_bf2(bf_res(v.x), bf_res(v.y));
    }
}

// ---------------- weight prep: transpose + bf16 hi/lo split ----------------
__global__ void k_prep_w(const float* __restrict__ Wl1, const float* __restrict__ Wr1,
                         const float* __restrict__ Wl2, const float* __restrict__ Wr2) {
    int idx = blockIdx.x * blockDim.x + threadIdx.x;    // 0..65535
    int l = idx >> 15;
    int r = idx & 32767;
    int k = r >> 7, nn = r & 127;
    const float* Wl = l ? Wl2 : Wl1;
    const float* Wr = l ? Wr2 : Wr1;
    float v = (k < 128) ? Wl[k * 128 + nn] : Wr[(k - 128) * 128 + nn];
    int chunk = k >> 5, kk = k & 31;
    g_Bh[l][chunk][nn * 32 + kk] = __float2bfloat16(v);
    g_Bl[l][chunk][nn * 32 + kk] = __float2bfloat16(bf_res(v));
}

// ---------------- fused aggregate + HMMA GEMM ----------------
// 512 threads: warps 0-7 compute, warps 8-15 gather-aggregate.
// out[128 x 128] = [agg | self] @ B + bias; K=256 in 8 chunks of 32.
// smem: aggA hi 32K | aggA lo 32K | 2 stages x 32K | bias 512 = 131584 B
#define AGG_L_OFF   32768
#define STAGE_OFF   65536
#define STAGE_BYTES 32768
#define SM_BIAS_OFF 131072
#define SMEM_TOTAL  131584

__global__ __launch_bounds__(512, 1) void k_fused(
        const float* __restrict__ x, const float* __restrict__ bias,
        float* __restrict__ out, int n, int layer,
        int self_sel, int out_fp32, int do_relu) {
    extern __shared__ char smem[];
    uint32_t sb = smem_u32(smem);
    float* sbias = (float*)(smem + SM_BIAS_OFF);

    int tid = threadIdx.x, wid = tid >> 5, lid = tid & 31;
    int n0 = blockIdx.x * 128;
    if (tid < 128) sbias[tid] = bias[tid];
    __syncthreads();

    // ================= gather warps (8-15) =================
    if (wid >= 8) {
        const float* __restrict__ gsrc = self_sel ? (const float*)g_hf : x;
        int gwl = wid - 8;                         // 0..7
        // per-lane smem write selectors: lane covers feats 4l..4l+3
        int chL  = lid >> 3;                       // k-chunk 0..3
        uint32_t ciL  = ((uint32_t)lid & 7) >> 1;
        uint32_t remL = ((uint32_t)lid & 1) * 8;
        #pragma unroll 1
        for (int i = 0; i < 16; i++) {
            int row = gwl * 16 + i;
            int gn = n0 + row;
            float a0 = 0.f, a1 = 0.f, a2 = 0.f, a3 = 0.f;
            if (gn < n) {
                int deg = min(g_cursor[gn], CAP);
                const int* __restrict__ bk = &g_bucket[(size_t)gn * CAP];
                int e = 0;
                for (; e + 4 <= deg; e += 4) {
                    int4 s4 = *(const int4*)&bk[e];
                    float4 v0 = *(const float4*)&gsrc[(size_t)s4.x * D + lid * 4];
                    float4 v1 = *(const float4*)&gsrc[(size_t)s4.y * D + lid * 4];
                    float4 v2 = *(const float4*)&gsrc[(size_t)s4.z * D + lid * 4];
                    float4 v3 = *(const float4*)&gsrc[(size_t)s4.w * D + lid * 4];
                    a0 += (v0.x + v1.x) + (v2.x + v3.x);
                    a1 += (v0.y + v1.y) + (v2.y + v3.y);
                    a2 += (v0.z + v1.z) + (v2.z + v3.z);
                    a3 += (v0.w + v1.w) + (v2.w + v3.w);
                }
                for (; e < deg; e++) {
                    float4 v = *(const float4*)&gsrc[(size_t)bk[e] * D + lid * 4];
                    a0 += v.x; a1 += v.y; a2 += v.z; a3 += v.w;
                }
                float inv = 1.0f / (float)max(deg, 1);
                a0 *= inv; a1 *= inv; a2 *= inv; a3 *= inv;
            }
            uint32_t woff = (uint32_t)chL * 8192 + SWZ(row, ciL) + remL;
            *(uint2*)(smem + woff) =
                make_uint2(pack_bf2(a0, a1), pack_bf2(a2, a3));
            *(uint2*)(smem + AGG_L_OFF + woff) =
                make_uint2(pack_bf2(bf_res(a0), bf_res(a1)),
                           pack_bf2(bf_res(a2), bf_res(a3)));
        }
        __threadfence_block();
        BAR_ARRIVE_1_512();
        return;
    }

    // ================= compute warps (0-7) =================
    const uint32_t* __restrict__ selfH = self_sel ? g_hh : g_xh;
    const uint32_t* __restrict__ selfL = self_sel ? g_hl : g_xl;
    int widm = wid & 3, widn = wid >> 2;

    int lA_row = lid & 15, lA_ci = lid >> 4;
    int lB_row = (lid & 7) + ((lid >> 4) << 3), lB_ci = (lid >> 3) & 1;

    float acc[2][8][4];
    #pragma unroll
    for (int mt = 0; mt < 2; mt++)
        #pragma unroll
        for (int nt = 0; nt < 8; nt++)
            #pragma unroll
            for (int j = 0; j < 4; j++) acc[mt][nt][j] = 0.f;

    // stage loader: seq s -> chunk (s<4 ? s+4 : s-4)
    auto issue = [&](int s, int st) {
        int chunk = (s < 4) ? (s + 4) : (s - 4);
        const char* pBh = (const char*)&g_Bh[layer][chunk][0];
        const char* pBl = (const char*)&g_Bl[layer][chunk][0];
        uint32_t sa = sb + STAGE_OFF + (uint32_t)st * STAGE_BYTES;
        if (s < 4) {
            int koff = (chunk & 3) * 16;      // u32 offset within 256B row
            #pragma unroll
            for (int g = 0; g < 2; g++) {
                int idx = tid + g * 256;      // 0..511
                int row = idx >> 2, ci = idx & 3;
                int gn = n0 + row;
                uint32_t ok = (gn < n) ? 16u : 0u;
                int gnc = (gn < n) ? gn : 0;
                const char* sh = (const char*)(selfH + (size_t)gnc * 64 + koff + ci * 4);
                const char* sl = (const char*)(selfL + (size_t)gnc * 64 + koff + ci * 4);
                uint32_t d0 = sa + SWZ(row, ci);
                cp16(d0,         sh, ok);
                cp16(d0 + 8192,  sl, ok);
                cp16(d0 + 16384, pBh + row * 64 + ci * 16, 16u);
                cp16(d0 + 24576, pBl + row * 64 + ci * 16, 16u);
            }
        } else {
            #pragma unroll
            for (int g = 0; g < 2; g++) {
                int idx = tid + g * 256;
                int row = idx >> 2, ci = idx & 3;
                uint32_t d0 = sa + SWZ(row, ci);
                cp16(d0 + 16384, pBh + row * 64 + ci * 16, 16u);
                cp16(d0 + 24576, pBl + row * 64 + ci * 16, 16u);
            }
        }
    };

    issue(0, 0); CP_COMMIT();

    #pragma unroll 1
    for (int s = 0; s < 8; s++) {
        if (s + 1 < 8) { issue(s + 1, (s + 1) & 1); CP_COMMIT(); CP_WAIT(1); }
        else           { CP_WAIT(0); }
        if (s == 4) BAR_SYNC_1_512();      // agg chunks ready in smem
        BAR_SYNC_2_256();

        uint32_t stg = sb + STAGE_OFF + (uint32_t)(s & 1) * STAGE_BYTES;
        uint32_t aBase, alBase;
        if (s < 4) { aBase = stg; alBase = stg + 8192; }
        else       { aBase = sb + (uint32_t)(s - 4) * 8192;
                     alBase = sb + AGG_L_OFF + (uint32_t)(s - 4) * 8192; }
        uint32_t bBase = stg + 16384;

        #pragma unroll
        for (int ks = 0; ks < 2; ks++) {
            int ciA = ks * 2 + lA_ci;
            uint32_t ah[2][4], al[2][4];
            #pragma unroll
            for (int mt = 0; mt < 2; mt++) {
                int row = widm * 32 + mt * 16 + lA_row;
                uint32_t off = SWZ(row, ciA);
                ldm_x4(ah[mt], aBase + off);
                ldm_x4(al[mt], alBase + off);
            }
            int ciB = ks * 2 + lB_ci;
            uint32_t boff[4];
            uint32_t bf[4][4];
            #pragma unroll
            for (int g = 0; g < 4; g++) {
                int row = widn * 64 + g * 16 + lB_row;
                boff[g] = SWZ(row, ciB);
                ldm_x4(bf[g], bBase + boff[g]);
            }
            #pragma unroll
            for (int mt = 0; mt < 2; mt++)
                #pragma unroll
                for (int g = 0; g < 4; g++) {
                    mma16816(acc[mt][2 * g],     ah[mt], bf[g][0], bf[g][1]);
                    mma16816(acc[mt][2 * g + 1], ah[mt], bf[g][2], bf[g][3]);
                    mma16816(acc[mt][2 * g],     al[mt], bf[g][0], bf[g][1]);
                    mma16816(acc[mt][2 * g + 1], al[mt], bf[g][2], bf[g][3]);
                }
            #pragma unroll
            for (int g = 0; g < 4; g++)
                ldm_x4(bf[g], bBase + 8192 + boff[g]);
            #pragma unroll
            for (int mt = 0; mt < 2; mt++)
                #pragma unroll
                for (int g = 0; g < 4; g++) {
                    mma16816(acc[mt][2 * g],     ah[mt], bf[g][0], bf[g][1]);
                    mma16816(acc[mt][2 * g + 1], ah[mt], bf[g][2], bf[g][3]);
                }
        }
        BAR_SYNC_2_256();
    }

    // ---- epilogue ----
    int lr = lid >> 2, lc = (lid & 3) * 2;
    #pragma unroll
    for (int mt = 0; mt < 2; mt++) {
        #pragma unroll
        for (int pr = 0; pr < 2; pr++) {
            int gn = n0 + widm * 32 + mt * 16 + lr + pr * 8;
            if (gn >= n) continue;
            #pragma unroll
            for (int nt = 0; nt < 8; nt++) {
                int col = widn * 64 + nt * 8 + lc;
                float v0 = acc[mt][nt][pr * 2]     + sbias[col];
                float v1 = acc[mt][nt][pr * 2 + 1] + sbias[col + 1];
                if (do_relu) { v0 = fmaxf(v0, 0.f); v1 = fmaxf(v1, 0.f); }
                if (out_fp32) {
                    *(float2*)&out[(size_t)gn * D + col] = make_float2(v0, v1);
                } else {
                    size_t w = (size_t)gn * 64 + (col >> 1);
                    g_hh[w] = pack_bf2(v0, v1);
                    g_hl[w] = pack_bf2(bf_res(v0), bf_res(v1));
                    *(float2*)&g_hf[(size_t)gn * D + col] = make_float2(v0, v1);
                }
            }
        }
    }
}

// ---------------- launch ----------------
extern "C" void kernel_launch(void* const* d_in, const int* in_sizes, int n_in,
                              void* d_out, int out_size) {
    const float* x   = (const float*)d_in[0];
    const int*   ei  = (const int*)d_in[1];     // int32 edge_index
    const float* W1l = (const float*)d_in[2];
    const float* b1  = (const float*)d_in[3];
    const float* W1r = (const float*)d_in[4];
    const float* W2l = (const float*)d_in[5];
    const float* b2  = (const float*)d_in[6];
    const float* W2r = (const float*)d_in[7];
    float* out = (float*)d_out;

    int n = in_sizes[0] / D;
    int E = in_sizes[1] / 2;

    static cudaStream_t sB = nullptr;
    static cudaEvent_t evFork, evJoin;
    if (!sB) {
        cudaFuncSetAttribute(k_fused, cudaFuncAttributeMaxDynamicSharedMemorySize, SMEM_TOTAL);
        cudaStreamCreateWithFlags(&sB, cudaStreamNonBlocking);
        cudaEventCreateWithFlags(&evFork, cudaEventDisableTiming);
        cudaEventCreateWithFlags(&evJoin, cudaEventDisableTiming);
    }

    // fork: stream B does weight prep + x split while legacy stream builds graph
    cudaEventRecord(evFork, 0);
    cudaStreamWaitEvent(sB, evFork, 0);
    k_prep_w <<<256, 256, 0, sB>>>(W1l, W1r, W2l, W2r);
    k_split_x<<<(n * 64 + 255) / 256, 256, 0, sB>>>(x, n * 64);
    cudaEventRecord(evJoin, sB);

    k_zero   <<<(n + 255) / 256, 256>>>(n);
    k_scatter<<<(E / 4 + 255) / 256, 256>>>(ei, E, n);

    cudaStreamWaitEvent(0, evJoin, 0);   // join before layer 1

    int blocks = (n + 127) / 128;

    // layer 1: h = relu(agg(x)@W1l + x@W1r + b1)  -> planes + fp32
    k_fused<<<blocks, 512, SMEM_TOTAL>>>(x, b1, out, n, 0, /*self=x*/0, /*fp32*/0, /*relu*/1);

    // layer 2: out = agg(h)@W2l + h@W2r + b2  -> fp32 d_out
    k_fused<<<blocks, 512, SMEM_TOTAL>>>(x, b2, out, n, 1, /*self=h*/1, /*fp32*/1, /*relu*/0);
}

// round 8
// speedup vs baseline: 1.3575x; 1.3575x over previous
#include <cuda_runtime.h>
#include <cuda_bf16.h>
#include <cstdint>

// ---------------- problem constants ----------------
#define MAX_N 50000
#define MAX_E 800000
#define D 128
#define CAP 96          // bucket slots per node (deg ~ Poisson(16))

// ---------------- device-global scratch ----------------
__device__ int g_cursor[MAX_N];
__device__ int g_bucket[(size_t)MAX_N * CAP];
// bf16 hi/lo feature planes, each [node][64] u32 (= 128 bf16 per row, 256B)
__device__ __align__(128) uint32_t g_xh[(size_t)MAX_N * 64];
__device__ __align__(128) uint32_t g_xl[(size_t)MAX_N * 64];
__device__ __align__(128) uint32_t g_ah[(size_t)MAX_N * 64];
__device__ __align__(128) uint32_t g_al[(size_t)MAX_N * 64];
__device__ __align__(128) uint32_t g_hh[(size_t)MAX_N * 64];
__device__ __align__(128) uint32_t g_hl[(size_t)MAX_N * 64];
// fp32 partial accumulator (self@Wr + b)
__device__ __align__(128) float g_part[(size_t)MAX_N * D];
// bf16 hi/lo weight images, transposed: [layer][chunk(8)][n=128][k=32]
// chunks 0-3 = Wl (agg), 4-7 = Wr (self)
__device__ __align__(128) __nv_bfloat16 g_Bh[2][8][128 * 32];
__device__ __align__(128) __nv_bfloat16 g_Bl[2][8][128 * 32];

// ---------------- small helpers ----------------
__device__ __forceinline__ uint32_t pack_bf2(float a, float b) {
    __nv_bfloat162 t;
    t.x = __float2bfloat16(a);
    t.y = __float2bfloat16(b);
    return *reinterpret_cast<uint32_t*>(&t);
}
__device__ __forceinline__ float bf_res(float v) {
    return v - __bfloat162float(__float2bfloat16(v));
}
__device__ __forceinline__ float bf_lo(uint32_t u) { return __uint_as_float(u << 16); }
__device__ __forceinline__ float bf_hi(uint32_t u) { return __uint_as_float(u & 0xFFFF0000u); }

__device__ __forceinline__ uint32_t smem_u32(const void* p) {
    uint32_t a;
    asm("{ .reg .u64 t; cvta.to.shared.u64 t, %1; cvt.u32.u64 %0, t; }" : "=r"(a) : "l"(p));
    return a;
}
__device__ __forceinline__ void ldm_x4(uint32_t* r, uint32_t addr) {
    asm volatile("ldmatrix.sync.aligned.m8n8.x4.shared.b16 {%0,%1,%2,%3}, [%4];"
                 : "=r"(r[0]), "=r"(r[1]), "=r"(r[2]), "=r"(r[3]) : "r"(addr));
}
__device__ __forceinline__ void mma16816(float* d, const uint32_t* a, uint32_t b0, uint32_t b1) {
    asm volatile("mma.sync.aligned.m16n8k16.row.col.f32.bf16.bf16.f32 "
                 "{%0,%1,%2,%3}, {%4,%5,%6,%7}, {%8,%9}, {%0,%1,%2,%3};"
                 : "+f"(d[0]), "+f"(d[1]), "+f"(d[2]), "+f"(d[3])
                 : "r"(a[0]), "r"(a[1]), "r"(a[2]), "r"(a[3]), "r"(b0), "r"(b1));
}
__device__ __forceinline__ void cp16(uint32_t dst, const void* src, uint32_t sz) {
    asm volatile("cp.async.cg.shared.global [%0], [%1], 16, %2;"
                 :: "r"(dst), "l"(src), "r"(sz) : "memory");
}
#define CP_COMMIT()  asm volatile("cp.async.commit_group;" ::: "memory")
#define CP_WAIT(N)   asm volatile("cp.async.wait_group %0;" :: "n"(N) : "memory")

// XOR swizzle: 64B rows, 4x16B chunks; conflict-free for ldmatrix
#define SWZ(row, ci) (((uint32_t)(row) << 6) + (((((ci) ^ ((row) >> 1)) & 3)) << 4))

// ---------------- graph build: single-pass bucket scatter ----------------
__global__ void k_zero(int n) {
    int i = blockIdx.x * blockDim.x + threadIdx.x;
    if (i < n) g_cursor[i] = 0;
}
__global__ void k_scatter(const int* __restrict__ ei, int E2, int n) {
    int t = blockIdx.x * blockDim.x + threadIdx.x;   // handles 2 edges
    if (t < E2) {
        int2 sp = ((const int2*)ei)[t];
        int2 dp = ((const int2*)(ei + 2 * E2))[t];
        int d0 = min(max(dp.x, 0), n - 1), s0 = min(max(sp.x, 0), n - 1);
        int d1 = min(max(dp.y, 0), n - 1), s1 = min(max(sp.y, 0), n - 1);
        int p0 = atomicAdd(&g_cursor[d0], 1);
        if (p0 < CAP) g_bucket[(size_t)d0 * CAP + p0] = s0;
        int p1 = atomicAdd(&g_cursor[d1], 1);
        if (p1 < CAP) g_bucket[(size_t)d1 * CAP + p1] = s1;
    }
}

// ---------------- x -> bf16 hi/lo planes ----------------
__global__ void k_split_x(const float* __restrict__ x, int total64) {
    int i = blockIdx.x * blockDim.x + threadIdx.x;
    if (i < total64) {
        float2 v = ((const float2*)x)[i];
        g_xh[i] = pack_bf2(v.x, v.y);
        g_xl[i] = pack_bf2(bf_res(v.x), bf_res(v.y));
    }
}

// ---------------- weight prep: transpose + bf16 hi/lo split ----------------
__global__ void k_prep_w(const float* __restrict__ Wl1, const float* __restrict__ Wr1,
                         const float* __restrict__ Wl2, const float* __restrict__ Wr2) {
    int idx = blockIdx.x * blockDim.x + threadIdx.x;    // 0..65535
    int l = idx >> 15;
    int r = idx & 32767;
    int k = r >> 7, nn = r & 127;
    const float* Wl = l ? Wl2 : Wl1;
    const float* Wr = l ? Wr2 : Wr1;
    float v = (k < 128) ? Wl[k * 128 + nn] : Wr[(k - 128) * 128 + nn];
    int chunk = k >> 5, kk = k & 31;
    g_Bh[l][chunk][nn * 32 + kk] = __float2bfloat16(v);
    g_Bl[l][chunk][nn * 32 + kk] = __float2bfloat16(bf_res(v));
}

// ---------------- aggregation (warp per node) ----------------
// layer 1: gather fp32 x directly (no split_x dependency)
__global__ __launch_bounds__(256) void k_agg_x(const float* __restrict__ x, int n) {
    int gw = (blockIdx.x * blockDim.x + threadIdx.x) >> 5;
    int lane = threadIdx.x & 31;
    if (gw >= n) return;
    int deg = min(g_cursor[gw], CAP);
    float inv = 1.0f / (float)max(deg, 1);
    const int* __restrict__ bk = &g_bucket[(size_t)gw * CAP];
    float a0 = 0.f, a1 = 0.f, a2 = 0.f, a3 = 0.f;
    #pragma unroll 2
    for (int e = 0; e < deg; e++) {
        int s = bk[e];
        float4 v = *(const float4*)&x[(size_t)s * D + lane * 4];
        a0 += v.x; a1 += v.y; a2 += v.z; a3 += v.w;
    }
    a0 *= inv; a1 *= inv; a2 *= inv; a3 *= inv;
    size_t w = (size_t)gw * 64 + lane * 2;
    g_ah[w]     = pack_bf2(a0, a1);
    g_ah[w + 1] = pack_bf2(a2, a3);
    g_al[w]     = pack_bf2(bf_res(a0), bf_res(a1));
    g_al[w + 1] = pack_bf2(bf_res(a2), bf_res(a3));
}

// layer 2: gather h hi/lo planes
__global__ __launch_bounds__(256) void k_agg_h(int n) {
    int gw = (blockIdx.x * blockDim.x + threadIdx.x) >> 5;
    int lane = threadIdx.x & 31;
    if (gw >= n) return;
    int deg = min(g_cursor[gw], CAP);
    float inv = 1.0f / (float)max(deg, 1);
    const int* __restrict__ bk = &g_bucket[(size_t)gw * CAP];
    float a0 = 0.f, a1 = 0.f, a2 = 0.f, a3 = 0.f;
    #pragma unroll 2
    for (int e = 0; e < deg; e++) {
        int s = bk[e];
        size_t o = (size_t)s * 64 + lane * 2;
        uint2 uh = *(const uint2*)&g_hh[o];
        uint2 ul = *(const uint2*)&g_hl[o];
        a0 += bf_lo(uh.x) + bf_lo(ul.x);
        a1 += bf_hi(uh.x) + bf_hi(ul.x);
        a2 += bf_lo(uh.y) + bf_lo(ul.y);
        a3 += bf_hi(uh.y) + bf_hi(ul.y);
    }
    a0 *= inv; a1 *= inv; a2 *= inv; a3 *= inv;
    size_t w = (size_t)gw * 64 + lane * 2;
    g_ah[w]     = pack_bf2(a0, a1);
    g_ah[w + 1] = pack_bf2(a2, a3);
    g_al[w]     = pack_bf2(bf_res(a0), bf_res(a1));
    g_al[w + 1] = pack_bf2(bf_res(a2), bf_res(a3));
}

// ---------------- half-K HMMA GEMM (K=128, 4 chunks, 2-stage pipeline) ----------------
// mode 0: g_part = A@W + bias           (self half, chunks 4-7)
// mode 1: h = relu(A@W + g_part) -> planes (agg half L1, chunks 0-3)
// mode 2: out = A@W + g_part  (fp32)      (agg half L2, chunks 0-3)
#define STAGE_BYTES 32768
#define SM_BIAS_OFF 65536
#define SMEM_TOTAL  66048

__global__ __launch_bounds__(256, 2) void k_gemm_half(
        const float* __restrict__ bias, float* __restrict__ out,
        int n, int layer, int selA, int chunk_base, int mode) {
    extern __shared__ char smem[];
    uint32_t sb = smem_u32(smem);
    float* sbias = (float*)(smem + SM_BIAS_OFF);

    int tid = threadIdx.x, wid = tid >> 5, lid = tid & 31;
    int widm = wid & 3, widn = wid >> 2;
    int n0 = blockIdx.x * 128;
    if (tid < 128) sbias[tid] = bias[tid];

    const uint32_t* __restrict__ pAh = (selA == 0) ? g_xh : (selA == 1) ? g_hh : g_ah;
    const uint32_t* __restrict__ pAl = (selA == 0) ? g_xl : (selA == 1) ? g_hl : g_al;

    int lA_row = lid & 15, lA_ci = lid >> 4;
    int lB_row = (lid & 7) + ((lid >> 4) << 3), lB_ci = (lid >> 3) & 1;

    float acc[2][8][4];
    #pragma unroll
    for (int mt = 0; mt < 2; mt++)
        #pragma unroll
        for (int nt = 0; nt < 8; nt++)
            #pragma unroll
            for (int j = 0; j < 4; j++) acc[mt][nt][j] = 0.f;

    auto issue = [&](int c, int st) {
        int chunk = chunk_base + c;
        const char* pBh = (const char*)&g_Bh[layer][chunk][0];
        const char* pBl = (const char*)&g_Bl[layer][chunk][0];
        uint32_t sa = sb + st * STAGE_BYTES;
        int koff = c * 16;   // u32 offset within 256B plane row
        #pragma unroll
        for (int g = 0; g < 2; g++) {
            int idx = tid + g * 256;          // 0..511
            int row = idx >> 2, ci = idx & 3;
            int gn = n0 + row;
            uint32_t ok = (gn < n) ? 16u : 0u;
            int gnc = (gn < n) ? gn : 0;
            const char* sh = (const char*)(pAh + (size_t)gnc * 64 + koff + ci * 4);
            const char* sl = (const char*)(pAl + (size_t)gnc * 64 + koff + ci * 4);
            uint32_t d0 = sa + SWZ(row, ci);
            cp16(d0,         sh, ok);
            cp16(d0 + 8192,  sl, ok);
            cp16(d0 + 16384, pBh + row * 64 + ci * 16, 16u);
            cp16(d0 + 24576, pBl + row * 64 + ci * 16, 16u);
        }
    };

    issue(0, 0); CP_COMMIT();

    #pragma unroll 1
    for (int c = 0; c < 4; c++) {
        if (c < 3) { issue(c + 1, (c + 1) & 1); CP_COMMIT(); CP_WAIT(1); }
        else       { CP_WAIT(0); }
        __syncthreads();

        uint32_t base = sb + (c & 1) * STAGE_BYTES;
        #pragma unroll
        for (int ks = 0; ks < 2; ks++) {
            int ciA = ks * 2 + lA_ci;
            uint32_t ah[2][4], al[2][4];
            #pragma unroll
            for (int mt = 0; mt < 2; mt++) {
                int row = widm * 32 + mt * 16 + lA_row;
                uint32_t off = SWZ(row, ciA);
                ldm_x4(ah[mt], base + off);
                ldm_x4(al[mt], base + 8192 + off);
            }
            int ciB = ks * 2 + lB_ci;
            uint32_t boff[4];
            uint32_t bf[4][4];
            #pragma unroll
            for (int g = 0; g < 4; g++) {
                int row = widn * 64 + g * 16 + lB_row;
                boff[g] = SWZ(row, ciB);
                ldm_x4(bf[g], base + 16384 + boff[g]);
            }
            #pragma unroll
            for (int mt = 0; mt < 2; mt++)
                #pragma unroll
                for (int g = 0; g < 4; g++) {
                    mma16816(acc[mt][2 * g],     ah[mt], bf[g][0], bf[g][1]);
                    mma16816(acc[mt][2 * g + 1], ah[mt], bf[g][2], bf[g][3]);
                    mma16816(acc[mt][2 * g],     al[mt], bf[g][0], bf[g][1]);
                    mma16816(acc[mt][2 * g + 1], al[mt], bf[g][2], bf[g][3]);
                }
            #pragma unroll
            for (int g = 0; g < 4; g++)
                ldm_x4(bf[g], base + 24576 + boff[g]);
            #pragma unroll
            for (int mt = 0; mt < 2; mt++)
                #pragma unroll
                for (int g = 0; g < 4; g++) {
                    mma16816(acc[mt][2 * g],     ah[mt], bf[g][0], bf[g][1]);
                    mma16816(acc[mt][2 * g + 1], ah[mt], bf[g][2], bf[g][3]);
                }
        }
        __syncthreads();
    }

    // ---- epilogue ----
    int lr = lid >> 2, lc = (lid & 3) * 2;
    #pragma unroll
    for (int mt = 0; mt < 2; mt++) {
        #pragma unroll
        for (int pr = 0; pr < 2; pr++) {
            int gn = n0 + widm * 32 + mt * 16 + lr + pr * 8;
            if (gn >= n) continue;
            #pragma unroll
            for (int nt = 0; nt < 8; nt++) {
                int col = widn * 64 + nt * 8 + lc;
                float v0 = acc[mt][nt][pr * 2];
                float v1 = acc[mt][nt][pr * 2 + 1];
                if (mode == 0) {
                    v0 += sbias[col]; v1 += sbias[col + 1];
                    *(float2*)&g_part[(size_t)gn * D + col] = make_float2(v0, v1);
                } else {
                    float2 p = *(const float2*)&g_part[(size_t)gn * D + col];
                    v0 += p.x; v1 += p.y;
                    if (mode == 1) {
                        v0 = fmaxf(v0, 0.f); v1 = fmaxf(v1, 0.f);
                        size_t w = (size_t)gn * 64 + (col >> 1);
                        g_hh[w] = pack_bf2(v0, v1);
                        g_hl[w] = pack_bf2(bf_res(v0), bf_res(v1));
                    } else {
                        *(float2*)&out[(size_t)gn * D + col] = make_float2(v0, v1);
                    }
                }
            }
        }
    }
}

// ---------------- launch ----------------
extern "C" void kernel_launch(void* const* d_in, const int* in_sizes, int n_in,
                              void* d_out, int out_size) {
    const float* x   = (const float*)d_in[0];
    const int*   ei  = (const int*)d_in[1];     // int32 edge_index
    const float* W1l = (const float*)d_in[2];
    const float* b1  = (const float*)d_in[3];
    const float* W1r = (const float*)d_in[4];
    const float* W2l = (const float*)d_in[5];
    const float* b2  = (const float*)d_in[6];
    const float* W2r = (const float*)d_in[7];
    float* out = (float*)d_out;

    int n = in_sizes[0] / D;
    int E = in_sizes[1] / 2;

    static cudaStream_t sB = nullptr;
    static cudaEvent_t evFork, ev1, ev2, ev3;
    if (!sB) {
        cudaFuncSetAttribute(k_gemm_half, cudaFuncAttributeMaxDynamicSharedMemorySize, SMEM_TOTAL);
        cudaStreamCreateWithFlags(&sB, cudaStreamNonBlocking);
        cudaEventCreateWithFlags(&evFork, cudaEventDisableTiming);
        cudaEventCreateWithFlags(&ev1, cudaEventDisableTiming);
        cudaEventCreateWithFlags(&ev2, cudaEventDisableTiming);
        cudaEventCreateWithFlags(&ev3, cudaEventDisableTiming);
    }

    int agg_blocks  = (n * 32 + 255) / 256;
    int gemm_blocks = (n + 127) / 128;

    // fork: stream B preps weights/planes and runs self-half of layer 1
    cudaEventRecord(evFork, 0);
    cudaStreamWaitEvent(sB, evFork, 0);
    k_prep_w <<<256, 256, 0, sB>>>(W1l, W1r, W2l, W2r);
    k_split_x<<<(n * 64 + 255) / 256, 256, 0, sB>>>(x, n * 64);
    k_gemm_half<<<gemm_blocks, 256, SMEM_TOTAL, sB>>>(b1, out, n, 0, /*selA=x*/0, 4, /*mode*/0);
    cudaEventRecord(ev1, sB);

    // main: graph build + layer-1 aggregation (gathers fp32 x; no split dep)
    k_zero   <<<(n + 255) / 256, 256>>>(n);
    k_scatter<<<(E / 2 + 255) / 256, 256>>>(ei, E / 2, n);
    k_agg_x  <<<agg_blocks, 256>>>(x, n);

    // join, then agg-half of layer 1 (h = relu(agg@W1l + part))
    cudaStreamWaitEvent(0, ev1, 0);
    k_gemm_half<<<gemm_blocks, 256, SMEM_TOTAL>>>(b1, out, n, 0, /*selA=agg*/2, 0, /*mode*/1);
    cudaEventRecord(ev2, 0);

    // fork: self-half of layer 2 on sB, overlapped with agg2 on main
    cudaStreamWaitEvent(sB, ev2, 0);
    k_gemm_half<<<gemm_blocks, 256, SMEM_TOTAL, sB>>>(b2, out, n, 1, /*selA=h*/1, 4, /*mode*/0);
    cudaEventRecord(ev3, sB);

    k_agg_h<<<agg_blocks, 256>>>(n);

    // join, then agg-half of layer 2 (out = agg@W2l + part)
    cudaStreamWaitEvent(0, ev3, 0);
    k_gemm_half<<<gemm_blocks, 256, SMEM_TOTAL>>>(b2, out, n, 1, /*selA=agg*/2, 0, /*mode*/2);
}

// round 9
// speedup vs baseline: 1.6716x; 1.2313x over previous
#include <cuda_runtime.h>
#include <cuda_bf16.h>
#include <cstdint>

// ---------------- problem constants ----------------
#define MAX_N 50000
#define MAX_E 800000
#define D 128
#define CAP 96          // bucket slots per node (deg ~ Poisson(16))

// ---------------- device-global scratch ----------------
__device__ int g_cursor[MAX_N];
__device__ int g_bucket[(size_t)MAX_N * CAP];
// bf16 hi/lo feature planes, each [node][64] u32 (= 128 bf16 per row, 256B)
__device__ __align__(128) uint32_t g_xh[(size_t)MAX_N * 64];
__device__ __align__(128) uint32_t g_xl[(size_t)MAX_N * 64];
__device__ __align__(128) uint32_t g_ah[(size_t)MAX_N * 64];
__device__ __align__(128) uint32_t g_al[(size_t)MAX_N * 64];
__device__ __align__(128) uint32_t g_hh[(size_t)MAX_N * 64];
__device__ __align__(128) uint32_t g_hl[(size_t)MAX_N * 64];
// bf16 hi/lo weight images, transposed: [layer][chunk(8)][n=128][k=32]
__device__ __align__(128) __nv_bfloat16 g_Bh[2][8][128 * 32];
__device__ __align__(128) __nv_bfloat16 g_Bl[2][8][128 * 32];

// ---------------- small helpers ----------------
__device__ __forceinline__ uint32_t pack_bf2(float a, float b) {
    __nv_bfloat162 t;
    t.x = __float2bfloat16(a);
    t.y = __float2bfloat16(b);
    return *reinterpret_cast<uint32_t*>(&t);
}
__device__ __forceinline__ float bf_res(float v) {
    return v - __bfloat162float(__float2bfloat16(v));
}
__device__ __forceinline__ float bf_lo(uint32_t u) { return __uint_as_float(u << 16); }
__device__ __forceinline__ float bf_hi(uint32_t u) { return __uint_as_float(u & 0xFFFF0000u); }

__device__ __forceinline__ uint32_t smem_u32(const void* p) {
    uint32_t a;
    asm("{ .reg .u64 t; cvta.to.shared.u64 t, %1; cvt.u32.u64 %0, t; }" : "=r"(a) : "l"(p));
    return a;
}
__device__ __forceinline__ void ldm_x4(uint32_t* r, uint32_t addr) {
    asm volatile("ldmatrix.sync.aligned.m8n8.x4.shared.b16 {%0,%1,%2,%3}, [%4];"
                 : "=r"(r[0]), "=r"(r[1]), "=r"(r[2]), "=r"(r[3]) : "r"(addr));
}
__device__ __forceinline__ void mma16816(float* d, const uint32_t* a, uint32_t b0, uint32_t b1) {
    asm volatile("mma.sync.aligned.m16n8k16.row.col.f32.bf16.bf16.f32 "
                 "{%0,%1,%2,%3}, {%4,%5,%6,%7}, {%8,%9}, {%0,%1,%2,%3};"
                 : "+f"(d[0]), "+f"(d[1]), "+f"(d[2]), "+f"(d[3])
                 : "r"(a[0]), "r"(a[1]), "r"(a[2]), "r"(a[3]), "r"(b0), "r"(b1));
}
__device__ __forceinline__ void cp16(uint32_t dst, const void* src, uint32_t sz) {
    asm volatile("cp.async.cg.shared.global [%0], [%1], 16, %2;"
                 :: "r"(dst), "l"(src), "r"(sz) : "memory");
}
#define CP_COMMIT()  asm volatile("cp.async.commit_group;" ::: "memory")
#define CP_WAIT(N)   asm volatile("cp.async.wait_group %0;" :: "n"(N) : "memory")

// XOR swizzle: 64B rows, 4x16B chunks; conflict-free for ldmatrix
#define SWZ(row, ci) (((uint32_t)(row) << 6) + (((((ci) ^ ((row) >> 1)) & 3)) << 4))

// ---------------- graph build: single-pass bucket scatter ----------------
__global__ void k_zero(int n) {
    int i = blockIdx.x * blockDim.x + threadIdx.x;
    if (i < n) g_cursor[i] = 0;
}
__global__ void k_scatter(const int* __restrict__ ei, int E2, int n) {
    int t = blockIdx.x * blockDim.x + threadIdx.x;   // handles 2 edges
    if (t < E2) {
        int2 sp = ((const int2*)ei)[t];
        int2 dp = ((const int2*)(ei + 2 * E2))[t];
        int d0 = min(max(dp.x, 0), n - 1), s0 = min(max(sp.x, 0), n - 1);
        int d1 = min(max(dp.y, 0), n - 1), s1 = min(max(sp.y, 0), n - 1);
        int p0 = atomicAdd(&g_cursor[d0], 1);
        if (p0 < CAP) g_bucket[(size_t)d0 * CAP + p0] = s0;
        int p1 = atomicAdd(&g_cursor[d1], 1);
        if (p1 < CAP) g_bucket[(size_t)d1 * CAP + p1] = s1;
    }
}

// ---------------- x -> bf16 hi/lo planes ----------------
__global__ void k_split_x(const float* __restrict__ x, int total64) {
    int i = blockIdx.x * blockDim.x + threadIdx.x;
    if (i < total64) {
        float2 v = ((const float2*)x)[i];
        g_xh[i] = pack_bf2(v.x, v.y);
        g_xl[i] = pack_bf2(bf_res(v.x), bf_res(v.y));
    }
}

// ---------------- weight prep: transpose + bf16 hi/lo split ----------------
__global__ void k_prep_w(const float* __restrict__ Wl1, const float* __restrict__ Wr1,
                         const float* __restrict__ Wl2, const float* __restrict__ Wr2) {
    int idx = blockIdx.x * blockDim.x + threadIdx.x;    // 0..65535
    int l = idx >> 15;
    int r = idx & 32767;
    int k = r >> 7, nn = r & 127;
    const float* Wl = l ? Wl2 : Wl1;
    const float* Wr = l ? Wr2 : Wr1;
    float v = (k < 128) ? Wl[k * 128 + nn] : Wr[(k - 128) * 128 + nn];
    int chunk = k >> 5, kk = k & 31;
    g_Bh[l][chunk][nn * 32 + kk] = __float2bfloat16(v);
    g_Bl[l][chunk][nn * 32 + kk] = __float2bfloat16(bf_res(v));
}

// ---------------- mean aggregation: warp per node, hi-plane-only gather ----
// reads 256B/row (bf16 hi plane); mean in fp32; writes agg hi/lo planes
__global__ __launch_bounds__(256) void k_agg(int n, int sel) {
    const uint32_t* __restrict__ fh = sel ? g_hh : g_xh;
    int gw = (blockIdx.x * blockDim.x + threadIdx.x) >> 5;
    int lane = threadIdx.x & 31;
    if (gw >= n) return;
    int deg = min(g_cursor[gw], CAP);
    float inv = 1.0f / (float)max(deg, 1);
    const int* __restrict__ bk = &g_bucket[(size_t)gw * CAP];
    float a0 = 0.f, a1 = 0.f, a2 = 0.f, a3 = 0.f;
    int e = 0;
    for (; e + 4 <= deg; e += 4) {
        int4 s4 = *(const int4*)&bk[e];
        uint2 u0 = *(const uint2*)&fh[(size_t)s4.x * 64 + lane * 2];
        uint2 u1 = *(const uint2*)&fh[(size_t)s4.y * 64 + lane * 2];
        uint2 u2 = *(const uint2*)&fh[(size_t)s4.z * 64 + lane * 2];
        uint2 u3 = *(const uint2*)&fh[(size_t)s4.w * 64 + lane * 2];
        a0 += (bf_lo(u0.x) + bf_lo(u1.x)) + (bf_lo(u2.x) + bf_lo(u3.x));
        a1 += (bf_hi(u0.x) + bf_hi(u1.x)) + (bf_hi(u2.x) + bf_hi(u3.x));
        a2 += (bf_lo(u0.y) + bf_lo(u1.y)) + (bf_lo(u2.y) + bf_lo(u3.y));
        a3 += (bf_hi(u0.y) + bf_hi(u1.y)) + (bf_hi(u2.y) + bf_hi(u3.y));
    }
    for (; e < deg; e++) {
        uint2 u = *(const uint2*)&fh[(size_t)bk[e] * 64 + lane * 2];
        a0 += bf_lo(u.x); a1 += bf_hi(u.x);
        a2 += bf_lo(u.y); a3 += bf_hi(u.y);
    }
    a0 *= inv; a1 *= inv; a2 *= inv; a3 *= inv;
    size_t w = (size_t)gw * 64 + lane * 2;
    g_ah[w]     = pack_bf2(a0, a1);
    g_ah[w + 1] = pack_bf2(a2, a3);
    g_al[w]     = pack_bf2(bf_res(a0), bf_res(a1));
    g_al[w + 1] = pack_bf2(bf_res(a2), bf_res(a3));
}

// ---------------- pipelined HMMA GEMM (2-stage) ----------------
// out[128 x 128] = [agg | self] @ B + bias; K=256 in 8 chunks of 32.
// dyn smem: 2 stages x (Ah 8K | Al 8K | Bh 8K | Bl 8K) + bias 512 = 66048 B
#define STAGE_BYTES 32768
#define SM_BIAS_OFF 65536
#define SMEM_TOTAL  66048

__global__ __launch_bounds__(256, 2) void k_gemm(
        const float* __restrict__ bias, float* __restrict__ out,
        int n, int layer, int self_sel, int out_fp32, int do_relu) {
    extern __shared__ char smem[];
    uint32_t sb = smem_u32(smem);
    float* sbias = (float*)(smem + SM_BIAS_OFF);

    int tid = threadIdx.x, wid = tid >> 5, lid = tid & 31;
    int widm = wid & 3, widn = wid >> 2;
    int n0 = blockIdx.x * 128;
    if (tid < 128) sbias[tid] = bias[tid];

    const uint32_t* __restrict__ selfH = self_sel ? g_hh : g_xh;
    const uint32_t* __restrict__ selfL = self_sel ? g_hl : g_xl;

    int lA_row = lid & 15, lA_ci = lid >> 4;
    int lB_row = (lid & 7) + ((lid >> 4) << 3), lB_ci = (lid >> 3) & 1;

    float acc[2][8][4];
    #pragma unroll
    for (int mt = 0; mt < 2; mt++)
        #pragma unroll
        for (int nt = 0; nt < 8; nt++)
            #pragma unroll
            for (int j = 0; j < 4; j++) acc[mt][nt][j] = 0.f;

    auto issue = [&](int c, int st) {
        const uint32_t* pAh = (c < 4) ? g_ah : selfH;
        const uint32_t* pAl = (c < 4) ? g_al : selfL;
        const char* pBh = (const char*)&g_Bh[layer][c][0];
        const char* pBl = (const char*)&g_Bl[layer][c][0];
        uint32_t sa = sb + st * STAGE_BYTES;
        int koff = (c & 3) * 16;   // u32 offset within 256B row
        #pragma unroll
        for (int g = 0; g < 2; g++) {
            int idx = tid + g * 256;          // 0..511
            int row = idx >> 2, ci = idx & 3;
            int gn = n0 + row;
            uint32_t ok = (gn < n) ? 16u : 0u;
            int gnc = (gn < n) ? gn : 0;
            const char* sh = (const char*)(pAh + (size_t)gnc * 64 + koff + ci * 4);
            const char* sl = (const char*)(pAl + (size_t)gnc * 64 + koff + ci * 4);
            uint32_t d0 = sa + SWZ(row, ci);
            cp16(d0,         sh, ok);
            cp16(d0 + 8192,  sl, ok);
            cp16(d0 + 16384, pBh + row * 64 + ci * 16, 16u);
            cp16(d0 + 24576, pBl + row * 64 + ci * 16, 16u);
        }
    };

    issue(0, 0);
    CP_COMMIT();

    #pragma unroll 1
    for (int c = 0; c < 8; c++) {
        if (c < 7) { issue(c + 1, (c + 1) & 1); CP_COMMIT(); CP_WAIT(1); }
        else       { CP_WAIT(0); }
        __syncthreads();

        uint32_t base = sb + (c & 1) * STAGE_BYTES;
        #pragma unroll
        for (int ks = 0; ks < 2; ks++) {
            int ciA = ks * 2 + lA_ci;
            uint32_t ah[2][4], al[2][4];
            #pragma unroll
            for (int mt = 0; mt < 2; mt++) {
                int row = widm * 32 + mt * 16 + lA_row;
                uint32_t off = SWZ(row, ciA);
                ldm_x4(ah[mt], base + off);
                ldm_x4(al[mt], base + 8192 + off);
            }
            int ciB = ks * 2 + lB_ci;
            uint32_t boff[4];
            uint32_t bf[4][4];
            #pragma unroll
            for (int g = 0; g < 4; g++) {
                int row = widn * 64 + g * 16 + lB_row;
                boff[g] = SWZ(row, ciB);
                ldm_x4(bf[g], base + 16384 + boff[g]);
            }
            #pragma unroll
            for (int mt = 0; mt < 2; mt++)
                #pragma unroll
                for (int g = 0; g < 4; g++) {
                    mma16816(acc[mt][2 * g],     ah[mt], bf[g][0], bf[g][1]);
                    mma16816(acc[mt][2 * g + 1], ah[mt], bf[g][2], bf[g][3]);
                    mma16816(acc[mt][2 * g],     al[mt], bf[g][0], bf[g][1]);
                    mma16816(acc[mt][2 * g + 1], al[mt], bf[g][2], bf[g][3]);
                }
            #pragma unroll
            for (int g = 0; g < 4; g++)
                ldm_x4(bf[g], base + 24576 + boff[g]);
            #pragma unroll
            for (int mt = 0; mt < 2; mt++)
                #pragma unroll
                for (int g = 0; g < 4; g++) {
                    mma16816(acc[mt][2 * g],     ah[mt], bf[g][0], bf[g][1]);
                    mma16816(acc[mt][2 * g + 1], ah[mt], bf[g][2], bf[g][3]);
                }
        }
        __syncthreads();
    }

    // ---- epilogue ----
    int lr = lid >> 2, lc = (lid & 3) * 2;
    #pragma unroll
    for (int mt = 0; mt < 2; mt++) {
        #pragma unroll
        for (int pr = 0; pr < 2; pr++) {
            int gn = n0 + widm * 32 + mt * 16 + lr + pr * 8;
            if (gn >= n) continue;
            #pragma unroll
            for (int nt = 0; nt < 8; nt++) {
                int col = widn * 64 + nt * 8 + lc;
                float v0 = acc[mt][nt][pr * 2]     + sbias[col];
                float v1 = acc[mt][nt][pr * 2 + 1] + sbias[col + 1];
                if (do_relu) { v0 = fmaxf(v0, 0.f); v1 = fmaxf(v1, 0.f); }
                if (out_fp32) {
                    *(float2*)&out[(size_t)gn * D + col] = make_float2(v0, v1);
                } else {
                    size_t w = (size_t)gn * 64 + (col >> 1);
                    g_hh[w] = pack_bf2(v0, v1);
                    g_hl[w] = pack_bf2(bf_res(v0), bf_res(v1));
                }
            }
        }
    }
}

// ---------------- launch ----------------
extern "C" void kernel_launch(void* const* d_in, const int* in_sizes, int n_in,
                              void* d_out, int out_size) {
    const float* x   = (const float*)d_in[0];
    const int*   ei  = (const int*)d_in[1];     // int32 edge_index
    const float* W1l = (const float*)d_in[2];
    const float* b1  = (const float*)d_in[3];
    const float* W1r = (const float*)d_in[4];
    const float* W2l = (const float*)d_in[5];
    const float* b2  = (const float*)d_in[6];
    const float* W2r = (const float*)d_in[7];
    float* out = (float*)d_out;

    int n = in_sizes[0] / D;
    int E = in_sizes[1] / 2;

    static cudaStream_t sB = nullptr;
    static cudaEvent_t evFork, evJoin;
    if (!sB) {
        cudaFuncSetAttribute(k_gemm, cudaFuncAttributeMaxDynamicSharedMemorySize, SMEM_TOTAL);
        cudaStreamCreateWithFlags(&sB, cudaStreamNonBlocking);
        cudaEventCreateWithFlags(&evFork, cudaEventDisableTiming);
        cudaEventCreateWithFlags(&evJoin, cudaEventDisableTiming);
    }

    // fork: stream B does weight prep + x split while legacy stream builds graph
    cudaEventRecord(evFork, 0);
    cudaStreamWaitEvent(sB, evFork, 0);
    k_prep_w <<<256, 256, 0, sB>>>(W1l, W1r, W2l, W2r);
    k_split_x<<<(n * 64 + 255) / 256, 256, 0, sB>>>(x, n * 64);
    cudaEventRecord(evJoin, sB);

    k_zero   <<<(n + 255) / 256, 256>>>(n);
    k_scatter<<<(E / 2 + 255) / 256, 256>>>(ei, E / 2, n);

    cudaStreamWaitEvent(0, evJoin, 0);   // join before layer 1

    int agg_blocks  = (n * 32 + 255) / 256;
    int gemm_blocks = (n + 127) / 128;

    // layer 1: h = relu(agg(x)@W1l + x@W1r + b1)  -> hi/lo planes
    k_agg <<<agg_blocks, 256>>>(n, 0);
    k_gemm<<<gemm_blocks, 256, SMEM_TOTAL>>>(b1, out, n, 0, /*self=x*/0, /*fp32*/0, /*relu*/1);

    // layer 2: out = agg(h)@W2l + h@W2r + b2  -> fp32 d_out
    k_agg <<<agg_blocks, 256>>>(n, 1);
    k_gemm<<<gemm_blocks, 256, SMEM_TOTAL>>>(b2, out, n, 1, /*self=h*/1, /*fp32*/1, /*relu*/0);
}